// round 14
// baseline (speedup 1.0000x reference)
#include <cuda_runtime.h>

#define NS      4
#define NA      8192
#define NC      8
#define THR2    1.21f
#define GRID    32
#define GRIDXY  (GRID * GRID)
#define CELLS   (GRID * GRID * GRID)     // 32768
#define ORIGIN  (-17.632f)
#define INV_H   (1.0f / 1.102f)          // h = 1.102 > 1.1 clash radius
#define NBLK    128                      // build grid: <= #SMs -> co-resident
#define SBLK    (NS * NA / 8)            // search blocks: warp per atom, 8/blk

// Device-global scratch. Replay invariants: g_counts, g_npc, g_cellCounts,
// g_sd, g_sync* are zero on entry (zero-init at load; consumers re-zero).
__device__ int g_counts[NS * NC * NC];
__device__ int g_npc[NC];
__device__ int g_sd;                     // search blocks done
__device__ int g_sync0, g_sync1, g_sync2;
__device__ int g_partial[NS * 32];       // per-chunk scan partials
__device__ int g_chain[NA];
__device__ __align__(16) int    g_cellCounts[NS][CELLS];
__device__ __align__(16) int    g_cellStarts[NS][CELLS + 4];
__device__ __align__(16) float4 g_pk[NS][NA];   // (x,y,z,q) cell-sorted
__device__ int    g_meta[NS][NA];               // chain of sorted atom

__device__ __forceinline__ int cellco(float v) {
    int c = __float2int_rd((v - ORIGIN) * INV_H);
    return min(GRID - 1, max(0, c));
}

// Grid barrier: valid because all NBLK blocks are co-resident (NBLK <= SMs).
__device__ __forceinline__ void gsync(int* ctr, int* prev) {
    __threadfence();
    __syncthreads();
    if (threadIdx.x == 0) {
        int r = atomicAdd(ctr, 1);
        if (prev && r == NBLK - 1) *prev = 0;
        while (*(volatile int*)ctr < NBLK) __nanosleep(32);
    }
    __syncthreads();
    __threadfence();
}

// ---------------------------------------------------------------------------
// build: hist -> scan -> scatter in ONE persistent kernel (3 barriers).
// Identical to the R13 build (validated).
__global__ __launch_bounds__(256) void build_kernel(
    const float* __restrict__ coord,
    const int*   __restrict__ asym,
    const int*   __restrict__ a2t)
{
    __shared__ float s_c[768];
    __shared__ int s_w[8];
    __shared__ int s_off;

    int tid = threadIdx.x;
    int t   = blockIdx.x * 256 + tid;    // 0 .. NS*NA-1 (exactly grid size)
    int s   = t >> 13;
    int a   = t & (NA - 1);

    // ---- P1: coalesced coord stage, histogram (rank = atomic return) ------
    {
        const float* cb = coord + (size_t)blockIdx.x * 768;
        s_c[tid]       = cb[tid];
        s_c[tid + 256] = cb[tid + 256];
        s_c[tid + 512] = cb[tid + 512];
    }
    __syncthreads();
    float x = s_c[3 * tid], y = s_c[3 * tid + 1], z = s_c[3 * tid + 2];
    float q = fmaf(x, x, fmaf(y, y, z * z));
    int cell = cellco(x) + GRID * cellco(y) + GRIDXY * cellco(z);
    int rank = atomicAdd(&g_cellCounts[s][cell], 1);
    if (t < NA) {
        int ch = asym[a2t[t]];
        g_chain[t] = ch;
        atomicAdd(&g_npc[ch], 1);
    }

    gsync(&g_sync0, 0);

    // ---- P2a: local scan of this block's 1024-cell chunk ------------------
    int sb = blockIdx.x >> 5;
    int ch = blockIdx.x & 31;
    int base = ch * 1024 + tid * 4;
    int4 v = *(const int4*)(g_cellCounts[sb] + base);
    int sum = v.x + v.y + v.z + v.w;

    int lane = tid & 31, wid = tid >> 5;
    int inc = sum;
#pragma unroll
    for (int d = 1; d < 32; d <<= 1) {
        int u = __shfl_up_sync(0xFFFFFFFF, inc, d);
        if (lane >= d) inc += u;
    }
    if (lane == 31) s_w[wid] = inc;
    __syncthreads();
    if (tid < 8) {
        int wv = s_w[tid];
        int wi = wv;
#pragma unroll
        for (int d = 1; d < 8; d <<= 1) {
            int u = __shfl_up_sync(0xFF, wi, d);
            if (tid >= d) wi += u;
        }
        s_w[tid] = wi - wv;
        if (tid == 7) g_partial[sb * 32 + ch] = wi;
    }
    __syncthreads();
    int run = s_w[wid] + (inc - sum);
    *(int4*)(g_cellCounts[sb] + base) = make_int4(0, 0, 0, 0);

    gsync(&g_sync1, &g_sync0);

    // ---- P2b: add cross-chunk offset, store starts -------------------------
    if (tid < 32) {
        int pv = (tid < ch) ? g_partial[sb * 32 + tid] : 0;
#pragma unroll
        for (int d = 16; d > 0; d >>= 1)
            pv += __shfl_down_sync(0xFFFFFFFF, pv, d);
        if (tid == 0) s_off = pv;
    }
    __syncthreads();
    int off = s_off;
    int4 o;
    o.x = run + off;
    o.y = o.x + v.x;
    o.z = o.y + v.y;
    o.w = o.z + v.z;
    *(int4*)(g_cellStarts[sb] + base) = o;
    if (ch == 31 && tid == 255) g_cellStarts[sb][CELLS] = NA;

    gsync(&g_sync2, &g_sync1);

    // ---- P3: scatter from registers ----------------------------------------
    int pos = g_cellStarts[s][cell] + rank;
    g_pk[s][pos]   = make_float4(x, y, z, q);
    g_meta[s][pos] = g_chain[a];
}

// ---------------------------------------------------------------------------
// search: WARP-COOPERATIVE — one warp per sorted atom. Lanes 0-4 fetch the 5
// forward row-ranges (rows (z+1, y-1..y+1), (z, y+1), own-row tail j>k; same
// ranges/once-counting as the validated segmented kernel). Ranges are
// flattened into a dense candidate list via shuffles; the warp sweeps it
// 32-wide with zero trip-count divergence. meta is loaded lazily on hit only.
// fp32 predicate association identical to the accepted brute-force kernel.
// Last-arriving block runs the fused finalize and resets replay counters.
// out layout: [ has (256 floats) | details (512 floats, (tot, rel)) ]
__global__ __launch_bounds__(256, 8) void search_kernel(float* __restrict__ out) {
    __shared__ int scnt[NC * NC];
    __shared__ int s_last;
    int tid  = threadIdx.x;
    int lane = tid & 31;
    int wid  = tid >> 5;
    if (tid < NC * NC) scnt[tid] = 0;
    __syncthreads();

    int gw = blockIdx.x * 8 + wid;       // 0 .. NS*NA-1: one warp per atom
    int s  = gw >> 13;
    int k  = gw & (NA - 1);

    float4 p  = g_pk[s][k];              // broadcast load (all lanes same addr)
    int    ci = g_meta[s][k];

    float m2x = -2.0f * p.x, m2y = -2.0f * p.y, m2z = -2.0f * p.z;
    float K   = p.w - THR2;

    int cx = cellco(p.x), cy = cellco(p.y), cz = cellco(p.z);
    int x0 = max(cx - 1, 0), x1 = min(cx + 1, GRID - 1);

    // lanes 0-4 compute their row range
    const int* st = g_cellStarts[s];
    int lo = 0, len = 0;
    if (lane < 5) {
        int dy = (lane < 3) ? (lane - 1) : ((lane == 3) ? 1 : 0);
        int dz = (lane < 3) ? 1 : 0;
        int ty = cy + dy, tz = cz + dz;
        if (((unsigned)ty < GRID) & ((unsigned)tz < GRID)) {
            int row = GRID * ty + GRIDXY * tz;
            int l = st[row + x0];
            int h = st[row + x1 + 1];
            if (lane == 4) l = k + 1;    // own-row tail (covers fwd-x cell too)
            lo  = l;
            len = max(h - l, 0);
        }
    }
    // broadcast ranges + prefix
    int lo0 = __shfl_sync(0xFFFFFFFF, lo, 0), n0 = __shfl_sync(0xFFFFFFFF, len, 0);
    int lo1 = __shfl_sync(0xFFFFFFFF, lo, 1), n1 = __shfl_sync(0xFFFFFFFF, len, 1);
    int lo2 = __shfl_sync(0xFFFFFFFF, lo, 2), n2 = __shfl_sync(0xFFFFFFFF, len, 2);
    int lo3 = __shfl_sync(0xFFFFFFFF, lo, 3), n3 = __shfl_sync(0xFFFFFFFF, len, 3);
    int lo4 = __shfl_sync(0xFFFFFFFF, lo, 4), n4 = __shfl_sync(0xFFFFFFFF, len, 4);
    int p1 = n0, p2 = p1 + n1, p3 = p2 + n2, p4 = p3 + n3, T = p4 + n4;

    const float4* pk = g_pk[s];
    const int*    mt = g_meta[s];
    int bucket = ci * NC;

    for (int f = lane; f < T; f += 32) {
        int j = f + lo0;                 // segment select, branch-free
        if (f >= p1) j = f - p1 + lo1;
        if (f >= p2) j = f - p2 + lo2;
        if (f >= p3) j = f - p3 + lo3;
        if (f >= p4) j = f - p4 + lo4;
        float4 a = pk[j];
        float d = fmaf(m2z, a.z, fmaf(m2y, a.y, fmaf(m2x, a.x, a.w))) + K;
        if (d < 0.0f) {                  // lazy meta load: hits only
            int m = mt[j];
            if (m != ci) atomicAdd(&scnt[bucket + m], 1);
        }
    }

    __syncthreads();
    if (tid < NC * NC) {
        int v = scnt[tid];
        if (v) atomicAdd(&g_counts[s * NC * NC + tid], v);
    }
    __threadfence();
    __syncthreads();
    if (tid == 0) {
        int r = atomicAdd(&g_sd, 1);
        s_last = (r == SBLK - 1);
        if (s_last) { g_sd = 0; g_sync2 = 0; }   // reset replay counters
    }
    __syncthreads();
    if (!s_last) return;

    // ---- fused finalize (256 threads -> one (sample, a, b) each) ----
    {
        int fs = tid >> 6;
        int r  = tid & 63;
        int a  = r >> 3;
        int b  = r & 7;

        int tot_i = 0;
        if (a != b)
            tot_i = __ldcg(&g_counts[fs * NC * NC + a * NC + b]) +
                    __ldcg(&g_counts[fs * NC * NC + b * NC + a]);
        float tot = (float)tot_i;
        float mn  = (float)min(__ldcg(&g_npc[a]), __ldcg(&g_npc[b]));
        float rel = tot / mn;
        bool  has = (tot > 100.0f) || (rel > 0.5f);

        out[tid]                        = has ? 1.0f : 0.0f;
        out[NS * NC * NC + 2 * tid]     = tot;
        out[NS * NC * NC + 2 * tid + 1] = rel;

        __syncthreads();
        g_counts[tid] = 0;
        if (tid < NC) g_npc[tid] = 0;
    }
}

// ---------------------------------------------------------------------------
extern "C" void kernel_launch(void* const* d_in, const int* in_sizes, int n_in,
                              void* d_out, int out_size) {
    const float* coord = (const float*)d_in[0];   // [S, N, 3] f32
    const int*   asym  = (const int*)  d_in[1];   // [N_TOKENS] i32
    const int*   a2t   = (const int*)  d_in[2];   // [N] i32
    float*       out   = (float*)d_out;

    build_kernel <<<NBLK, 256>>>(coord, asym, a2t);
    search_kernel<<<SBLK, 256>>>(out);
}